// round 15
// baseline (speedup 1.0000x reference)
#include <cuda_runtime.h>
#include <math.h>

#define BB 4
#define TT 2048
#define EE 1024
#define HH 64
#define MM (BB*TT)

// device scratch (module statics: allocation-free)
__device__ float g_q[MM*HH];
__device__ float g_k[MM*HH];
__device__ float g_v[MM*HH];
// proj K-split partials: [kh][mat][row][col]
__device__ float g_pp[2*3*MM*HH];
// split-KV partials: pidx = (b*32 + qtile)*4 + chunk   (chunk of 8 KV tiles)
__device__ float g_po[512*64*64];
__device__ float g_ml[512*64*2];

__device__ __forceinline__ unsigned f2tf32(float f) {
    unsigned u;
    asm("cvt.rna.tf32.f32 %0, %1;" : "=r"(u) : "f"(f));
    return u;
}
__device__ __forceinline__ unsigned u2tf32(unsigned ub) {
    unsigned u;
    asm("cvt.rna.tf32.f32 %0, %1;" : "=r"(u) : "f"(__uint_as_float(ub)));
    return u;
}
__device__ __forceinline__ float ex2(float x) {
    float y;
    asm("ex2.approx.ftz.f32 %0, %1;" : "=f"(y) : "f"(x));
    return y;
}
__device__ __forceinline__ void mma_tf32(float c[4], unsigned a0, unsigned a1,
                                         unsigned a2, unsigned a3,
                                         unsigned b0, unsigned b1) {
    asm volatile(
        "mma.sync.aligned.m16n8k8.row.col.f32.tf32.tf32.f32 "
        "{%0,%1,%2,%3}, {%4,%5,%6,%7}, {%8,%9}, {%0,%1,%2,%3};"
        : "+f"(c[0]), "+f"(c[1]), "+f"(c[2]), "+f"(c[3])
        : "r"(a0), "r"(a1), "r"(a2), "r"(a3), "r"(b0), "r"(b1));
}
#define LDSM4(r0,r1,r2,r3,addr) \
    asm volatile("ldmatrix.sync.aligned.m8n8.x4.shared.b16 {%0,%1,%2,%3}, [%4];" \
                 : "=r"(r0), "=r"(r1), "=r"(r2), "=r"(r3) : "r"(addr))

__device__ __forceinline__ void cp16(void* smem, const void* gmem) {
    unsigned sa = (unsigned)__cvta_generic_to_shared(smem);
    asm volatile("cp.async.cg.shared.global [%0], [%1], 16;" :: "r"(sa), "l"(gmem));
}
#define CP_COMMIT() asm volatile("cp.async.commit_group;")
#define CP_WAIT0()  asm volatile("cp.async.wait_group 0;")
#define CP_WAIT1()  asm volatile("cp.async.wait_group 1;")

// ---------------------------------------------------------------------------
// Kernel 1: FUSED QKV projection, K-split across 2 blocks.
// grid (128, 2): x = 64-row tile, y = kh (K columns [kh*512, kh*512+512)).
// block 256 (8 warps), warp tiling 2m x 2n x 2k, 16 K-chunks of 32,
// 3-stage cp.async ring, pitch 36.  Raw fp32 partials -> g_pp[kh].
// ---------------------------------------------------------------------------
#define PJ_PITCH 36
#define PJ_MATF  (64*PJ_PITCH)
#define PJ_STAGE (4*PJ_MATF)
#define PJ_SM_FLOATS (3*PJ_STAGE)

__global__ __launch_bounds__(256) void proj_kernel(
    const float* __restrict__ x,
    const float* __restrict__ Wq,
    const float* __restrict__ Wk,
    const float* __restrict__ Wv)
{
    extern __shared__ __align__(16) float psm[];

    const int row0 = blockIdx.x * 64;
    const int kh   = blockIdx.y;
    const int tid  = threadIdx.x;
    const int wid  = tid >> 5, l = tid & 31;
    const int g    = l >> 2, tg = l & 3;
    const int m0   = (wid & 1) * 32;
    const int n0   = ((wid >> 1) & 1) * 32;
    const int kg   = wid >> 2;

    const float* srcp[4];
    srcp[0] = x + (size_t)row0 * EE + kh * 512;
    srcp[1] = Wq + kh * 512;
    srcp[2] = Wk + kh * 512;
    srcp[3] = Wv + kh * 512;

#define PPREF(kc) { \
    float* stage = psm + ((kc) % 3) * PJ_STAGE; \
    _Pragma("unroll") for (int mmat = 0; mmat < 4; mmat++) { \
        _Pragma("unroll") for (int t = 0; t < 2; t++) { \
            int idx = tid + t * 256; \
            int row = idx >> 3, u = idx & 7; \
            cp16(stage + mmat * PJ_MATF + row * PJ_PITCH + u * 4, \
                 srcp[mmat] + (size_t)row * EE + (kc) * 32 + u * 4); \
        } \
    } \
    CP_COMMIT(); }

    float acc[3][2][4][4];
#pragma unroll
    for (int mat = 0; mat < 3; mat++)
#pragma unroll
        for (int mi = 0; mi < 2; mi++)
#pragma unroll
            for (int nf = 0; nf < 4; nf++)
#pragma unroll
                for (int i = 0; i < 4; i++) acc[mat][mi][nf][i] = 0.0f;

    const unsigned sb = (unsigned)__cvta_generic_to_shared(psm);
    const unsigned aoffA[2] = {
        (unsigned)((m0 +      (l & 15)) * PJ_PITCH + ((l & 16) >> 2)),
        (unsigned)((m0 + 16 + (l & 15)) * PJ_PITCH + ((l & 16) >> 2)) };
    const unsigned boffB[2] = {
        (unsigned)((n0 +      (l & 7) + ((l & 16) >> 1)) * PJ_PITCH + ((l & 8) >> 1)),
        (unsigned)((n0 + 16 + (l & 7) + ((l & 16) >> 1)) * PJ_PITCH + ((l & 8) >> 1)) };

    PPREF(0); PPREF(1);

    for (int j = 0; j < 16; j++) {
        if (j < 15) { CP_WAIT1(); } else { CP_WAIT0(); }
        __syncthreads();

        const unsigned stg = sb + (j % 3) * (PJ_STAGE * 4);
#pragma unroll
        for (int k8 = 0; k8 < 2; k8++) {
            const unsigned kk = (kg * 16 + k8 * 8) * 4;
            unsigned a[2][4];
#pragma unroll
            for (int mi = 0; mi < 2; mi++) {
                LDSM4(a[mi][0], a[mi][1], a[mi][2], a[mi][3],
                      stg + aoffA[mi] * 4 + kk);
                a[mi][0] = u2tf32(a[mi][0]); a[mi][1] = u2tf32(a[mi][1]);
                a[mi][2] = u2tf32(a[mi][2]); a[mi][3] = u2tf32(a[mi][3]);
            }
#pragma unroll
            for (int mat = 0; mat < 3; mat++) {
                const unsigned mb = stg + (1 + mat) * (PJ_MATF * 4);
#pragma unroll
                for (int np = 0; np < 2; np++) {
                    unsigned b0, b1, b2, b3;
                    LDSM4(b0, b1, b2, b3, mb + boffB[np] * 4 + kk);
                    b0 = u2tf32(b0); b1 = u2tf32(b1);
                    b2 = u2tf32(b2); b3 = u2tf32(b3);
#pragma unroll
                    for (int mi = 0; mi < 2; mi++) {
                        mma_tf32(acc[mat][mi][np*2    ], a[mi][0], a[mi][1], a[mi][2], a[mi][3], b0, b1);
                        mma_tf32(acc[mat][mi][np*2 + 1], a[mi][0], a[mi][1], a[mi][2], a[mi][3], b2, b3);
                    }
                }
            }
        }
        if (j + 2 < 16) PPREF(j + 2);
    }
#undef PPREF

    // ---- internal k-split reduction: warps 4-7 publish, 0-3 combine ----
    __syncthreads();
    if (kg == 1) {
        float* red = psm + (tid - 128) * 96;
#pragma unroll
        for (int mat = 0; mat < 3; mat++)
#pragma unroll
            for (int mi = 0; mi < 2; mi++)
#pragma unroll
                for (int nf = 0; nf < 4; nf++)
#pragma unroll
                    for (int i = 0; i < 4; i++)
                        red[((mat*2 + mi)*4 + nf)*4 + i] = acc[mat][mi][nf][i];
    }
    __syncthreads();
    if (kg == 0) {
        const float* red = psm + tid * 96;
        float* ppbase = g_pp + (size_t)kh * (3 * MM * HH);
#pragma unroll
        for (int mat = 0; mat < 3; mat++) {
            float* outp = ppbase + (size_t)mat * (MM * HH);
#pragma unroll
            for (int mi = 0; mi < 2; mi++) {
#pragma unroll
                for (int nf = 0; nf < 4; nf++) {
                    const float* rp = red + ((mat*2 + mi)*4 + nf)*4;
                    int col = n0 + nf * 8 + 2 * tg;
                    int r_lo = row0 + m0 + mi*16 + g;
                    float2 v0, v1;
                    v0.x = acc[mat][mi][nf][0] + rp[0];
                    v0.y = acc[mat][mi][nf][1] + rp[1];
                    v1.x = acc[mat][mi][nf][2] + rp[2];
                    v1.y = acc[mat][mi][nf][3] + rp[3];
                    *(float2*)(outp + (size_t)r_lo       * HH + col) = v0;
                    *(float2*)(outp + (size_t)(r_lo + 8) * HH + col) = v1;
                }
            }
        }
    }
}

// ---------------------------------------------------------------------------
// Kernel 1b: combine K-split partials + bias, tf32-round, -> g_q/g_k/g_v.
// grid 1536, block 256, one float4 per thread.
// ---------------------------------------------------------------------------
__global__ __launch_bounds__(256) void preduce_kernel(
    const float* __restrict__ bq, const float* __restrict__ bk,
    const float* __restrict__ bv)
{
    const int f = blockIdx.x * 256 + threadIdx.x;    // float4 index, 0..393215
    const int permat = MM * HH / 4;                  // 131072
    const int mat = f / permat;
    const int r   = f - mat * permat;                // float4 idx within matrix
    const int col = (r * 4) & (HH - 1);

    const float4 p0 = ((const float4*)g_pp)[f];
    const float4 p1 = ((const float4*)g_pp)[f + 3 * permat];
    const float* bias = (mat == 0) ? bq : (mat == 1) ? bk : bv;
    float4 o;
    o.x = __uint_as_float(f2tf32(p0.x + p1.x + bias[col    ]));
    o.y = __uint_as_float(f2tf32(p0.y + p1.y + bias[col + 1]));
    o.z = __uint_as_float(f2tf32(p0.z + p1.z + bias[col + 2]));
    o.w = __uint_as_float(f2tf32(p0.w + p1.w + bias[col + 3]));
    float* outp = (mat == 0) ? g_q : (mat == 1) ? g_k : g_v;
    ((float4*)outp)[r] = o;
}

// ---------------------------------------------------------------------------
// Kernel 2: causal flash attention (R14: 102KB smem, 2 blocks/SM).
// ---------------------------------------------------------------------------
#define PITCH 68
#define TILE_F (64*PITCH)
#define KS_OFF 0
#define VS_OFF (2*TILE_F)
#define PS_OFF (4*TILE_F)
#define SM_FLOATS (PS_OFF + 8*16*PITCH)
#define SCL 0.18033688011112042f

__device__ __forceinline__ void attn_prefetch(
    float* sm, const float* kbase, const float* vbase,
    int tid, int tbase, int nt, int j)
{
#pragma unroll
    for (int t = 0; t < 16; t++) {
        int cidf = tid + t * 256;
        int sel  = cidf >> 10;
        int cid  = cidf & 1023;
        int row  = cid >> 4, c16 = cid & 15;
        int jt   = 2 * j + (sel & 1);
        if (jt < nt) {
            const float* src = ((sel >> 1) ? vbase : kbase)
                               + ((size_t)((tbase + jt) * 64 + row)) * HH + c16 * 4;
            float* dst = sm + ((sel >> 1) ? VS_OFF : KS_OFF)
                         + (sel & 1) * TILE_F + row * PITCH + c16 * 4;
            cp16(dst, src);
        }
    }
}

__global__ __launch_bounds__(256, 2) void attn_kernel(float* __restrict__ out)
{
    extern __shared__ float sm[];

    const int b   = blockIdx.y;
    const int tid = threadIdx.x;
    const int wid = tid >> 5, l = tid & 31, g = l >> 2, tg = l & 3;
    const int mt  = wid & 3;
    const int s   = wid >> 2;

    int qi = 0, ch = 0;
    {
        int wl = blockIdx.x, acc = 0;
        for (int ii = 31; ii >= 0; ii--) {
            int nc = (ii + 8) >> 3;
            if (wl < acc + nc) { qi = ii; ch = wl - acc; break; }
            acc += nc;
        }
    }
    const int qt0    = qi * 64;
    const int ntiles = qi + 1;
    const int nch    = (qi + 8) >> 3;
    const int tbase  = ch * 8;
    int nt = ntiles - tbase; if (nt > 8) nt = 8;
    const int ns = (nt + 1) >> 1;

    const float* kbase = g_k + (size_t)b * TT * HH;
    const float* vbase = g_v + (size_t)b * TT * HH;

    {
        const float* qsrc = g_q + ((size_t)b * TT + qt0) * HH;
#pragma unroll
        for (int t = 0; t < 4; t++) {
            int cid = tid + t * 256;
            int row = cid >> 4, c16 = cid & 15;
            cp16(sm + PS_OFF + row * PITCH + c16 * 4, qsrc + row * HH + c16 * 4);
        }
        attn_prefetch(sm, kbase, vbase, tid, tbase, nt, 0);
        CP_COMMIT();
    }

    const unsigned smu = (unsigned)__cvta_generic_to_shared(sm);
    const unsigned a16off = ((l & 15) * PITCH + ((l & 16) >> 2)) * 4;
    const unsigned bkoff  = (((l & 7) + ((l & 16) >> 1)) * PITCH + ((l & 8) >> 1)) * 4;
    const unsigned ps_u32 = smu + (PS_OFF + wid * 16 * PITCH) * 4 + a16off;
    const unsigned qs_u32 = smu + (PS_OFF + mt * 16 * PITCH) * 4 + a16off;

    unsigned qreg[8][4];
    float o[8][4];
    float m_lo = -INFINITY, m_hi = -INFINITY, l_lo = 0.f, l_hi = 0.f;
#pragma unroll
    for (int n = 0; n < 8; n++)
#pragma unroll
        for (int i = 0; i < 4; i++) o[n][i] = 0.0f;

    float* Ps = sm + PS_OFF + wid * (16 * PITCH);

    for (int j = 0; j < ns; j++) {
        CP_WAIT0();
        __syncthreads();

        if (j == 0) {
#pragma unroll
            for (int k8 = 0; k8 < 8; k8++)
                LDSM4(qreg[k8][0], qreg[k8][1], qreg[k8][2], qreg[k8][3],
                      qs_u32 + k8 * 32);
            __syncthreads();
        }

        const int jt = 2 * j + s;
        if (jt < nt) {
            const int k0 = (tbase + jt) * 64;
            const unsigned kb_u32 = smu + (KS_OFF + s * TILE_F) * 4 + bkoff;
            const float* Vb = sm + VS_OFF + s * TILE_F;

            float sc[8][4];
#pragma unroll
            for (int n = 0; n < 8; n++)
#pragma unroll
                for (int i = 0; i < 4; i++) sc[n][i] = 0.0f;
#pragma unroll
            for (int k8 = 0; k8 < 8; k8++) {
#pragma unroll
                for (int n0p = 0; n0p < 4; n0p++) {
                    unsigned b0, b1, b2, b3;
                    LDSM4(b0, b1, b2, b3,
                          kb_u32 + n0p * (16 * PITCH * 4) + k8 * 32);
                    mma_tf32(sc[n0p*2    ], qreg[k8][0], qreg[k8][1], qreg[k8][2], qreg[k8][3], b0, b1);
                    mma_tf32(sc[n0p*2 + 1], qreg[k8][0], qreg[k8][1], qreg[k8][2], qreg[k8][3], b2, b3);
                }
            }

            const int t_lo = qt0 + mt*16 + g;
            const int t_hi = t_lo + 8;
            float mx_lo = -INFINITY, mx_hi = -INFINITY;
#pragma unroll
            for (int n0 = 0; n0 < 8; n0++) {
                int c0 = k0 + n0*8 + 2*tg, c1 = c0 + 1;
                sc[n0][0] = (c0 <= t_lo) ? sc[n0][0] * SCL : -INFINITY;
                sc[n0][1] = (c1 <= t_lo) ? sc[n0][1] * SCL : -INFINITY;
                sc[n0][2] = (c0 <= t_hi) ? sc[n0][2] * SCL : -INFINITY;
                sc[n0][3] = (c1 <= t_hi) ? sc[n0][3] * SCL : -INFINITY;
                mx_lo = fmaxf(mx_lo, fmaxf(sc[n0][0], sc[n0][1]));
                mx_hi = fmaxf(mx_hi, fmaxf(sc[n0][2], sc[n0][3]));
            }
            mx_lo = fmaxf(mx_lo, __shfl_xor_sync(0xffffffffu, mx_lo, 1));
            mx_lo = fmaxf(mx_lo, __shfl_xor_sync(0xffffffffu, mx_lo, 2));
            mx_hi = fmaxf(mx_hi, __shfl_xor_sync(0xffffffffu, mx_hi, 1));
            mx_hi = fmaxf(mx_hi, __shfl_xor_sync(0xffffffffu, mx_hi, 2));
            float mn_lo = fmaxf(m_lo, mx_lo);
            float mn_hi = fmaxf(m_hi, mx_hi);
            float f_lo = ex2(m_lo - mn_lo);
            float f_hi = ex2(m_hi - mn_hi);

            float sum_lo = 0.f, sum_hi = 0.f;
#pragma unroll
            for (int n0 = 0; n0 < 8; n0++) {
                float p0 = ex2(sc[n0][0] - mn_lo);
                float p1 = ex2(sc[n0][1] - mn_lo);
                float p2 = ex2(sc[n0][2] - mn_hi);
                float p3 = ex2(sc[n0][3] - mn_hi);
                sum_lo += p0 + p1;
                sum_hi += p2 + p3;
                float2 w0, w1;
                w0.x = __uint_as_float(f2tf32(p0)); w0.y = __uint_as_float(f2tf32(p1));
                w1.x = __uint_as_float(f2tf32(p2)); w1.y = __uint_as_float(f2tf32(p3));
                *(float2*)(Ps + (g    ) * PITCH + n0*8 + 2*tg) = w0;
                *(float2*)(Ps + (g + 8) * PITCH + n0*8 + 2*tg) = w1;
            }
            sum_lo += __shfl_xor_sync(0xffffffffu, sum_lo, 1);
            sum_lo += __shfl_xor_sync(0xffffffffu, sum_lo, 2);
            sum_hi += __shfl_xor_sync(0xffffffffu, sum_hi, 1);
            sum_hi += __shfl_xor_sync(0xffffffffu, sum_hi, 2);
            l_lo = l_lo * f_lo + sum_lo;
            l_hi = l_hi * f_hi + sum_hi;
            m_lo = mn_lo; m_hi = mn_hi;
#pragma unroll
            for (int n0 = 0; n0 < 8; n0++) {
                o[n0][0] *= f_lo; o[n0][1] *= f_lo;
                o[n0][2] *= f_hi; o[n0][3] *= f_hi;
            }
            __syncwarp();

#pragma unroll
            for (int k8 = 0; k8 < 8; k8++) {
                unsigned a0, a1, a2, a3;
                LDSM4(a0, a1, a2, a3, ps_u32 + k8 * 32);
#pragma unroll
                for (int n0 = 0; n0 < 8; n0++) {
                    unsigned b0 = __float_as_uint(Vb[(k8*8 + tg    ) * PITCH + n0*8 + g]);
                    unsigned b1 = __float_as_uint(Vb[(k8*8 + tg + 4) * PITCH + n0*8 + g]);
                    mma_tf32(o[n0], a0, a1, a2, a3, b0, b1);
                }
            }
        }
        __syncthreads();
        if (j + 1 < ns) {
            attn_prefetch(sm, kbase, vbase, tid, tbase, nt, j + 1);
            CP_COMMIT();
        }
    }

    __syncthreads();
    float* Om = sm + PS_OFF + mt * (16 * PITCH);
    float* Ml = sm + PS_OFF + 4 * (16 * PITCH) + mt * 32;
    if (s == 1) {
#pragma unroll
        for (int n0 = 0; n0 < 8; n0++) {
            *(float2*)(Om + (g    ) * PITCH + n0*8 + 2*tg) = make_float2(o[n0][0], o[n0][1]);
            *(float2*)(Om + (g + 8) * PITCH + n0*8 + 2*tg) = make_float2(o[n0][2], o[n0][3]);
        }
        Ml[g] = m_lo; Ml[g + 8] = m_hi;
        Ml[16 + g] = l_lo; Ml[16 + 8 + g] = l_hi;
    }
    __syncthreads();
    if (s == 0) {
        float m2_lo = Ml[g], m2_hi = Ml[g + 8];
        float l2_lo = Ml[16 + g], l2_hi = Ml[16 + 8 + g];
        float mf_lo = fmaxf(m_lo, m2_lo), mf_hi = fmaxf(m_hi, m2_hi);
        float a_lo = ex2(m_lo - mf_lo), b_lo = ex2(m2_lo - mf_lo);
        float a_hi = ex2(m_hi - mf_hi), b_hi = ex2(m2_hi - mf_hi);
        float lm_lo = l_lo * a_lo + l2_lo * b_lo;
        float lm_hi = l_hi * a_hi + l2_hi * b_hi;
        const int r_lo = mt*16 + g, r_hi = r_lo + 8;

        if (nch == 1) {
            float inv_lo = 1.0f / lm_lo, inv_hi = 1.0f / lm_hi;
#pragma unroll
            for (int n0 = 0; n0 < 8; n0++) {
                float2 o2l = *(float2*)(Om + (g    ) * PITCH + n0*8 + 2*tg);
                float2 o2h = *(float2*)(Om + (g + 8) * PITCH + n0*8 + 2*tg);
                float2 r0, r1;
                r0.x = (o[n0][0] * a_lo + o2l.x * b_lo) * inv_lo;
                r0.y = (o[n0][1] * a_lo + o2l.y * b_lo) * inv_lo;
                r1.x = (o[n0][2] * a_hi + o2h.x * b_hi) * inv_hi;
                r1.y = (o[n0][3] * a_hi + o2h.y * b_hi) * inv_hi;
                *(float2*)(out + ((size_t)b * TT + qt0 + r_lo) * HH + n0*8 + 2*tg) = r0;
                *(float2*)(out + ((size_t)b * TT + qt0 + r_hi) * HH + n0*8 + 2*tg) = r1;
            }
        } else {
            const int pidx = (b * 32 + qi) * 4 + ch;
            float* pod = g_po + (size_t)pidx * 4096;
#pragma unroll
            for (int n0 = 0; n0 < 8; n0++) {
                float2 o2l = *(float2*)(Om + (g    ) * PITCH + n0*8 + 2*tg);
                float2 o2h = *(float2*)(Om + (g + 8) * PITCH + n0*8 + 2*tg);
                float2 r0, r1;
                r0.x = o[n0][0] * a_lo + o2l.x * b_lo;
                r0.y = o[n0][1] * a_lo + o2l.y * b_lo;
                r1.x = o[n0][2] * a_hi + o2h.x * b_hi;
                r1.y = o[n0][3] * a_hi + o2h.y * b_hi;
                *(float2*)(pod + r_lo * 64 + n0*8 + 2*tg) = r0;
                *(float2*)(pod + r_hi * 64 + n0*8 + 2*tg) = r1;
            }
            if (tg == 0) {
                g_ml[pidx*128 + r_lo*2] = mf_lo; g_ml[pidx*128 + r_lo*2 + 1] = lm_lo;
                g_ml[pidx*128 + r_hi*2] = mf_hi; g_ml[pidx*128 + r_hi*2 + 1] = lm_hi;
            }
        }
    }
}

// ---------------------------------------------------------------------------
// Kernel 3: merge split-KV partials (qi >= 8).  grid (24, 4), block 256.
// ---------------------------------------------------------------------------
__global__ __launch_bounds__(256) void merge_kernel(float* __restrict__ out)
{
    const int qi  = 8 + blockIdx.x;
    const int b   = blockIdx.y;
    const int nch = (qi + 8) >> 3;
    const int tid = threadIdx.x;
    const int r   = tid >> 2;
    const int cg  = (tid & 3) * 16;
    const int pbase = (b * 32 + qi) * 4;

    float mv[4], lv[4], e[4];
    float mf = -INFINITY;
    for (int c = 0; c < nch; c++) {
        mv[c] = g_ml[(pbase + c)*128 + r*2];
        lv[c] = g_ml[(pbase + c)*128 + r*2 + 1];
        mf = fmaxf(mf, mv[c]);
    }
    float wsum = 0.f;
    for (int c = 0; c < nch; c++) { e[c] = ex2(mv[c] - mf); wsum += lv[c] * e[c]; }
    float inv = 1.0f / wsum;

    size_t obase = ((size_t)b * TT + qi * 64 + r) * HH;
#pragma unroll
    for (int c4 = 0; c4 < 4; c4++) {
        float4 a = make_float4(0.f, 0.f, 0.f, 0.f);
        for (int c = 0; c < nch; c++) {
            const float4 p = *(const float4*)(g_po + (size_t)(pbase + c)*4096 + r*64 + cg + c4*4);
            a.x += e[c]*p.x; a.y += e[c]*p.y; a.z += e[c]*p.z; a.w += e[c]*p.w;
        }
        a.x *= inv; a.y *= inv; a.z *= inv; a.w *= inv;
        *(float4*)(out + obase + cg + c4*4) = a;
    }
}

// ---------------------------------------------------------------------------
extern "C" void kernel_launch(void* const* d_in, const int* in_sizes, int n_in,
                              void* d_out, int out_size)
{
    const float* x  = (const float*)d_in[0];
    const float* Wq = (const float*)d_in[1];
    const float* bq = (const float*)d_in[2];
    const float* Wk = (const float*)d_in[3];
    const float* bk = (const float*)d_in[4];
    const float* Wv = (const float*)d_in[5];
    const float* bv = (const float*)d_in[6];
    float* out = (float*)d_out;

    const int proj_smem = PJ_SM_FLOATS * sizeof(float);   // 110592
    cudaFuncSetAttribute(proj_kernel, cudaFuncAttributeMaxDynamicSharedMemorySize, proj_smem);
    proj_kernel<<<dim3(MM / 64, 2), 256, proj_smem>>>(x, Wq, Wk, Wv);

    preduce_kernel<<<1536, 256>>>(bq, bk, bv);

    const int smem_bytes = SM_FLOATS * sizeof(float);     // 104448
    cudaFuncSetAttribute(attn_kernel, cudaFuncAttributeMaxDynamicSharedMemorySize, smem_bytes);
    attn_kernel<<<dim3(80, BB), 256, smem_bytes>>>(out);

    merge_kernel<<<dim3(24, BB), 256>>>(out);
}

// round 16
// speedup vs baseline: 1.1308x; 1.1308x over previous
#include <cuda_runtime.h>
#include <math.h>

#define BB 4
#define TT 2048
#define EE 1024
#define HH 64
#define MM (BB*TT)

// device scratch (module statics: allocation-free)
__device__ float g_q[MM*HH];
__device__ float g_k[MM*HH];
__device__ float g_v[MM*HH];
// split-KV partials: pidx = (b*32 + qtile)*4 + chunk   (chunk of 8 KV tiles)
__device__ float g_po[512*64*64];
__device__ float g_ml[512*64*2];

__device__ __forceinline__ unsigned f2tf32(float f) {
    unsigned u;
    asm("cvt.rna.tf32.f32 %0, %1;" : "=r"(u) : "f"(f));
    return u;
}
__device__ __forceinline__ unsigned u2tf32(unsigned ub) {
    unsigned u;
    asm("cvt.rna.tf32.f32 %0, %1;" : "=r"(u) : "f"(__uint_as_float(ub)));
    return u;
}
__device__ __forceinline__ float ex2(float x) {
    float y;
    asm("ex2.approx.ftz.f32 %0, %1;" : "=f"(y) : "f"(x));
    return y;
}
__device__ __forceinline__ void mma_tf32(float c[4], unsigned a0, unsigned a1,
                                         unsigned a2, unsigned a3,
                                         unsigned b0, unsigned b1) {
    asm volatile(
        "mma.sync.aligned.m16n8k8.row.col.f32.tf32.tf32.f32 "
        "{%0,%1,%2,%3}, {%4,%5,%6,%7}, {%8,%9}, {%0,%1,%2,%3};"
        : "+f"(c[0]), "+f"(c[1]), "+f"(c[2]), "+f"(c[3])
        : "r"(a0), "r"(a1), "r"(a2), "r"(a3), "r"(b0), "r"(b1));
}
#define LDSM4(r0,r1,r2,r3,addr) \
    asm volatile("ldmatrix.sync.aligned.m8n8.x4.shared.b16 {%0,%1,%2,%3}, [%4];" \
                 : "=r"(r0), "=r"(r1), "=r"(r2), "=r"(r3) : "r"(addr))

__device__ __forceinline__ void cp16(void* smem, const void* gmem) {
    unsigned sa = (unsigned)__cvta_generic_to_shared(smem);
    asm volatile("cp.async.cg.shared.global [%0], [%1], 16;" :: "r"(sa), "l"(gmem));
}
#define CP_COMMIT() asm volatile("cp.async.commit_group;")
#define CP_WAIT0()  asm volatile("cp.async.wait_group 0;")
#define CP_WAIT1()  asm volatile("cp.async.wait_group 1;")

// ---------------------------------------------------------------------------
// Kernel 1: FUSED QKV projection (R10/R14 configuration — fastest measured).
// grid 128 (64 rows/block), block 256 (8 warps).
// Warp tiling 2m x 2n x 2k; 32 K-chunks of 32; 3-stage cp.async(cg) ring.
// Pitch 36 floats.  kg=1 partials reduced into kg=0 via smem.
// ---------------------------------------------------------------------------
#define PJ_PITCH 36
#define PJ_MATF  (64*PJ_PITCH)
#define PJ_STAGE (4*PJ_MATF)
#define PJ_SM_FLOATS (3*PJ_STAGE)

__global__ __launch_bounds__(256) void proj_kernel(
    const float* __restrict__ x,
    const float* __restrict__ Wq, const float* __restrict__ bq,
    const float* __restrict__ Wk, const float* __restrict__ bk,
    const float* __restrict__ Wv, const float* __restrict__ bv)
{
    extern __shared__ __align__(16) float psm[];

    const int row0 = blockIdx.x * 64;
    const int tid  = threadIdx.x;
    const int wid  = tid >> 5, l = tid & 31;
    const int g    = l >> 2, tg = l & 3;
    const int m0   = (wid & 1) * 32;
    const int n0   = ((wid >> 1) & 1) * 32;
    const int kg   = wid >> 2;

    const float* srcp[4];
    srcp[0] = x + (size_t)row0 * EE;
    srcp[1] = Wq; srcp[2] = Wk; srcp[3] = Wv;

#define PPREF(kc) { \
    float* stage = psm + ((kc) % 3) * PJ_STAGE; \
    _Pragma("unroll") for (int mmat = 0; mmat < 4; mmat++) { \
        _Pragma("unroll") for (int t = 0; t < 2; t++) { \
            int idx = tid + t * 256; \
            int row = idx >> 3, u = idx & 7; \
            cp16(stage + mmat * PJ_MATF + row * PJ_PITCH + u * 4, \
                 srcp[mmat] + (size_t)row * EE + (kc) * 32 + u * 4); \
        } \
    } \
    CP_COMMIT(); }

    float acc[3][2][4][4];
#pragma unroll
    for (int mat = 0; mat < 3; mat++)
#pragma unroll
        for (int mi = 0; mi < 2; mi++)
#pragma unroll
            for (int nf = 0; nf < 4; nf++)
#pragma unroll
                for (int i = 0; i < 4; i++) acc[mat][mi][nf][i] = 0.0f;

    const unsigned sb = (unsigned)__cvta_generic_to_shared(psm);
    const unsigned aoffA[2] = {
        (unsigned)((m0 +      (l & 15)) * PJ_PITCH + ((l & 16) >> 2)),
        (unsigned)((m0 + 16 + (l & 15)) * PJ_PITCH + ((l & 16) >> 2)) };
    const unsigned boffB[2] = {
        (unsigned)((n0 +      (l & 7) + ((l & 16) >> 1)) * PJ_PITCH + ((l & 8) >> 1)),
        (unsigned)((n0 + 16 + (l & 7) + ((l & 16) >> 1)) * PJ_PITCH + ((l & 8) >> 1)) };

    PPREF(0); PPREF(1);

    for (int j = 0; j < 32; j++) {
        if (j < 31) { CP_WAIT1(); } else { CP_WAIT0(); }
        __syncthreads();

        const unsigned stg = sb + (j % 3) * (PJ_STAGE * 4);
#pragma unroll
        for (int k8 = 0; k8 < 2; k8++) {
            const unsigned kk = (kg * 16 + k8 * 8) * 4;
            unsigned a[2][4];
#pragma unroll
            for (int mi = 0; mi < 2; mi++) {
                LDSM4(a[mi][0], a[mi][1], a[mi][2], a[mi][3],
                      stg + aoffA[mi] * 4 + kk);
                a[mi][0] = u2tf32(a[mi][0]); a[mi][1] = u2tf32(a[mi][1]);
                a[mi][2] = u2tf32(a[mi][2]); a[mi][3] = u2tf32(a[mi][3]);
            }
#pragma unroll
            for (int mat = 0; mat < 3; mat++) {
                const unsigned mb = stg + (1 + mat) * (PJ_MATF * 4);
#pragma unroll
                for (int np = 0; np < 2; np++) {
                    unsigned b0, b1, b2, b3;
                    LDSM4(b0, b1, b2, b3, mb + boffB[np] * 4 + kk);
                    b0 = u2tf32(b0); b1 = u2tf32(b1);
                    b2 = u2tf32(b2); b3 = u2tf32(b3);
#pragma unroll
                    for (int mi = 0; mi < 2; mi++) {
                        mma_tf32(acc[mat][mi][np*2    ], a[mi][0], a[mi][1], a[mi][2], a[mi][3], b0, b1);
                        mma_tf32(acc[mat][mi][np*2 + 1], a[mi][0], a[mi][1], a[mi][2], a[mi][3], b2, b3);
                    }
                }
            }
        }
        if (j + 2 < 32) PPREF(j + 2);
    }
#undef PPREF

    __syncthreads();
    if (kg == 1) {
        float* red = psm + (tid - 128) * 96;
#pragma unroll
        for (int mat = 0; mat < 3; mat++)
#pragma unroll
            for (int mi = 0; mi < 2; mi++)
#pragma unroll
                for (int nf = 0; nf < 4; nf++)
#pragma unroll
                    for (int i = 0; i < 4; i++)
                        red[((mat*2 + mi)*4 + nf)*4 + i] = acc[mat][mi][nf][i];
    }
    __syncthreads();
    if (kg == 0) {
        const float* red = psm + tid * 96;
        const float* bs[3]  = {bq, bk, bv};
        float* outs[3] = {g_q, g_k, g_v};
#pragma unroll
        for (int mat = 0; mat < 3; mat++) {
#pragma unroll
            for (int mi = 0; mi < 2; mi++) {
#pragma unroll
                for (int nf = 0; nf < 4; nf++) {
                    const float* rp = red + ((mat*2 + mi)*4 + nf)*4;
                    int col = n0 + nf * 8 + 2 * tg;
                    float b0 = bs[mat][col], b1 = bs[mat][col + 1];
                    int r_lo = row0 + m0 + mi*16 + g;
                    float2 v0, v1;
                    v0.x = __uint_as_float(f2tf32(acc[mat][mi][nf][0] + rp[0] + b0));
                    v0.y = __uint_as_float(f2tf32(acc[mat][mi][nf][1] + rp[1] + b1));
                    v1.x = __uint_as_float(f2tf32(acc[mat][mi][nf][2] + rp[2] + b0));
                    v1.y = __uint_as_float(f2tf32(acc[mat][mi][nf][3] + rp[3] + b1));
                    *(float2*)(outs[mat] + (size_t)r_lo       * HH + col) = v0;
                    *(float2*)(outs[mat] + (size_t)(r_lo + 8) * HH + col) = v1;
                }
            }
        }
    }
}

// ---------------------------------------------------------------------------
// Kernel 2: causal flash attention (R14: 102KB smem, 2 blocks/SM).
// ---------------------------------------------------------------------------
#define PITCH 68
#define TILE_F (64*PITCH)
#define KS_OFF 0
#define VS_OFF (2*TILE_F)
#define PS_OFF (4*TILE_F)
#define SM_FLOATS (PS_OFF + 8*16*PITCH)
#define SCL 0.18033688011112042f

__device__ __forceinline__ void attn_prefetch(
    float* sm, const float* kbase, const float* vbase,
    int tid, int tbase, int nt, int j)
{
#pragma unroll
    for (int t = 0; t < 16; t++) {
        int cidf = tid + t * 256;
        int sel  = cidf >> 10;
        int cid  = cidf & 1023;
        int row  = cid >> 4, c16 = cid & 15;
        int jt   = 2 * j + (sel & 1);
        if (jt < nt) {
            const float* src = ((sel >> 1) ? vbase : kbase)
                               + ((size_t)((tbase + jt) * 64 + row)) * HH + c16 * 4;
            float* dst = sm + ((sel >> 1) ? VS_OFF : KS_OFF)
                         + (sel & 1) * TILE_F + row * PITCH + c16 * 4;
            cp16(dst, src);
        }
    }
}

__global__ __launch_bounds__(256, 2) void attn_kernel(float* __restrict__ out)
{
    extern __shared__ float sm[];

    const int b   = blockIdx.y;
    const int tid = threadIdx.x;
    const int wid = tid >> 5, l = tid & 31, g = l >> 2, tg = l & 3;
    const int mt  = wid & 3;
    const int s   = wid >> 2;

    int qi = 0, ch = 0;
    {
        int wl = blockIdx.x, acc = 0;
        for (int ii = 31; ii >= 0; ii--) {
            int nc = (ii + 8) >> 3;
            if (wl < acc + nc) { qi = ii; ch = wl - acc; break; }
            acc += nc;
        }
    }
    const int qt0    = qi * 64;
    const int ntiles = qi + 1;
    const int nch    = (qi + 8) >> 3;
    const int tbase  = ch * 8;
    int nt = ntiles - tbase; if (nt > 8) nt = 8;
    const int ns = (nt + 1) >> 1;

    const float* kbase = g_k + (size_t)b * TT * HH;
    const float* vbase = g_v + (size_t)b * TT * HH;

    {
        const float* qsrc = g_q + ((size_t)b * TT + qt0) * HH;
#pragma unroll
        for (int t = 0; t < 4; t++) {
            int cid = tid + t * 256;
            int row = cid >> 4, c16 = cid & 15;
            cp16(sm + PS_OFF + row * PITCH + c16 * 4, qsrc + row * HH + c16 * 4);
        }
        attn_prefetch(sm, kbase, vbase, tid, tbase, nt, 0);
        CP_COMMIT();
    }

    const unsigned smu = (unsigned)__cvta_generic_to_shared(sm);
    const unsigned a16off = ((l & 15) * PITCH + ((l & 16) >> 2)) * 4;
    const unsigned bkoff  = (((l & 7) + ((l & 16) >> 1)) * PITCH + ((l & 8) >> 1)) * 4;
    const unsigned ps_u32 = smu + (PS_OFF + wid * 16 * PITCH) * 4 + a16off;
    const unsigned qs_u32 = smu + (PS_OFF + mt * 16 * PITCH) * 4 + a16off;

    unsigned qreg[8][4];
    float o[8][4];
    float m_lo = -INFINITY, m_hi = -INFINITY, l_lo = 0.f, l_hi = 0.f;
#pragma unroll
    for (int n = 0; n < 8; n++)
#pragma unroll
        for (int i = 0; i < 4; i++) o[n][i] = 0.0f;

    float* Ps = sm + PS_OFF + wid * (16 * PITCH);

    for (int j = 0; j < ns; j++) {
        CP_WAIT0();
        __syncthreads();

        if (j == 0) {
#pragma unroll
            for (int k8 = 0; k8 < 8; k8++)
                LDSM4(qreg[k8][0], qreg[k8][1], qreg[k8][2], qreg[k8][3],
                      qs_u32 + k8 * 32);
            __syncthreads();
        }

        const int jt = 2 * j + s;
        if (jt < nt) {
            const int k0 = (tbase + jt) * 64;
            const unsigned kb_u32 = smu + (KS_OFF + s * TILE_F) * 4 + bkoff;
            const float* Vb = sm + VS_OFF + s * TILE_F;

            float sc[8][4];
#pragma unroll
            for (int n = 0; n < 8; n++)
#pragma unroll
                for (int i = 0; i < 4; i++) sc[n][i] = 0.0f;
#pragma unroll
            for (int k8 = 0; k8 < 8; k8++) {
#pragma unroll
                for (int n0p = 0; n0p < 4; n0p++) {
                    unsigned b0, b1, b2, b3;
                    LDSM4(b0, b1, b2, b3,
                          kb_u32 + n0p * (16 * PITCH * 4) + k8 * 32);
                    mma_tf32(sc[n0p*2    ], qreg[k8][0], qreg[k8][1], qreg[k8][2], qreg[k8][3], b0, b1);
                    mma_tf32(sc[n0p*2 + 1], qreg[k8][0], qreg[k8][1], qreg[k8][2], qreg[k8][3], b2, b3);
                }
            }

            const int t_lo = qt0 + mt*16 + g;
            const int t_hi = t_lo + 8;
            float mx_lo = -INFINITY, mx_hi = -INFINITY;
#pragma unroll
            for (int n0 = 0; n0 < 8; n0++) {
                int c0 = k0 + n0*8 + 2*tg, c1 = c0 + 1;
                sc[n0][0] = (c0 <= t_lo) ? sc[n0][0] * SCL : -INFINITY;
                sc[n0][1] = (c1 <= t_lo) ? sc[n0][1] * SCL : -INFINITY;
                sc[n0][2] = (c0 <= t_hi) ? sc[n0][2] * SCL : -INFINITY;
                sc[n0][3] = (c1 <= t_hi) ? sc[n0][3] * SCL : -INFINITY;
                mx_lo = fmaxf(mx_lo, fmaxf(sc[n0][0], sc[n0][1]));
                mx_hi = fmaxf(mx_hi, fmaxf(sc[n0][2], sc[n0][3]));
            }
            mx_lo = fmaxf(mx_lo, __shfl_xor_sync(0xffffffffu, mx_lo, 1));
            mx_lo = fmaxf(mx_lo, __shfl_xor_sync(0xffffffffu, mx_lo, 2));
            mx_hi = fmaxf(mx_hi, __shfl_xor_sync(0xffffffffu, mx_hi, 1));
            mx_hi = fmaxf(mx_hi, __shfl_xor_sync(0xffffffffu, mx_hi, 2));
            float mn_lo = fmaxf(m_lo, mx_lo);
            float mn_hi = fmaxf(m_hi, mx_hi);
            float f_lo = ex2(m_lo - mn_lo);
            float f_hi = ex2(m_hi - mn_hi);

            float sum_lo = 0.f, sum_hi = 0.f;
#pragma unroll
            for (int n0 = 0; n0 < 8; n0++) {
                float p0 = ex2(sc[n0][0] - mn_lo);
                float p1 = ex2(sc[n0][1] - mn_lo);
                float p2 = ex2(sc[n0][2] - mn_hi);
                float p3 = ex2(sc[n0][3] - mn_hi);
                sum_lo += p0 + p1;
                sum_hi += p2 + p3;
                float2 w0, w1;
                w0.x = __uint_as_float(f2tf32(p0)); w0.y = __uint_as_float(f2tf32(p1));
                w1.x = __uint_as_float(f2tf32(p2)); w1.y = __uint_as_float(f2tf32(p3));
                *(float2*)(Ps + (g    ) * PITCH + n0*8 + 2*tg) = w0;
                *(float2*)(Ps + (g + 8) * PITCH + n0*8 + 2*tg) = w1;
            }
            sum_lo += __shfl_xor_sync(0xffffffffu, sum_lo, 1);
            sum_lo += __shfl_xor_sync(0xffffffffu, sum_lo, 2);
            sum_hi += __shfl_xor_sync(0xffffffffu, sum_hi, 1);
            sum_hi += __shfl_xor_sync(0xffffffffu, sum_hi, 2);
            l_lo = l_lo * f_lo + sum_lo;
            l_hi = l_hi * f_hi + sum_hi;
            m_lo = mn_lo; m_hi = mn_hi;
#pragma unroll
            for (int n0 = 0; n0 < 8; n0++) {
                o[n0][0] *= f_lo; o[n0][1] *= f_lo;
                o[n0][2] *= f_hi; o[n0][3] *= f_hi;
            }
            __syncwarp();

#pragma unroll
            for (int k8 = 0; k8 < 8; k8++) {
                unsigned a0, a1, a2, a3;
                LDSM4(a0, a1, a2, a3, ps_u32 + k8 * 32);
#pragma unroll
                for (int n0 = 0; n0 < 8; n0++) {
                    unsigned b0 = __float_as_uint(Vb[(k8*8 + tg    ) * PITCH + n0*8 + g]);
                    unsigned b1 = __float_as_uint(Vb[(k8*8 + tg + 4) * PITCH + n0*8 + g]);
                    mma_tf32(o[n0], a0, a1, a2, a3, b0, b1);
                }
            }
        }
        __syncthreads();
        if (j + 1 < ns) {
            attn_prefetch(sm, kbase, vbase, tid, tbase, nt, j + 1);
            CP_COMMIT();
        }
    }

    __syncthreads();
    float* Om = sm + PS_OFF + mt * (16 * PITCH);
    float* Ml = sm + PS_OFF + 4 * (16 * PITCH) + mt * 32;
    if (s == 1) {
#pragma unroll
        for (int n0 = 0; n0 < 8; n0++) {
            *(float2*)(Om + (g    ) * PITCH + n0*8 + 2*tg) = make_float2(o[n0][0], o[n0][1]);
            *(float2*)(Om + (g + 8) * PITCH + n0*8 + 2*tg) = make_float2(o[n0][2], o[n0][3]);
        }
        Ml[g] = m_lo; Ml[g + 8] = m_hi;
        Ml[16 + g] = l_lo; Ml[16 + 8 + g] = l_hi;
    }
    __syncthreads();
    if (s == 0) {
        float m2_lo = Ml[g], m2_hi = Ml[g + 8];
        float l2_lo = Ml[16 + g], l2_hi = Ml[16 + 8 + g];
        float mf_lo = fmaxf(m_lo, m2_lo), mf_hi = fmaxf(m_hi, m2_hi);
        float a_lo = ex2(m_lo - mf_lo), b_lo = ex2(m2_lo - mf_lo);
        float a_hi = ex2(m_hi - mf_hi), b_hi = ex2(m2_hi - mf_hi);
        float lm_lo = l_lo * a_lo + l2_lo * b_lo;
        float lm_hi = l_hi * a_hi + l2_hi * b_hi;
        const int r_lo = mt*16 + g, r_hi = r_lo + 8;

        if (nch == 1) {
            float inv_lo = 1.0f / lm_lo, inv_hi = 1.0f / lm_hi;
#pragma unroll
            for (int n0 = 0; n0 < 8; n0++) {
                float2 o2l = *(float2*)(Om + (g    ) * PITCH + n0*8 + 2*tg);
                float2 o2h = *(float2*)(Om + (g + 8) * PITCH + n0*8 + 2*tg);
                float2 r0, r1;
                r0.x = (o[n0][0] * a_lo + o2l.x * b_lo) * inv_lo;
                r0.y = (o[n0][1] * a_lo + o2l.y * b_lo) * inv_lo;
                r1.x = (o[n0][2] * a_hi + o2h.x * b_hi) * inv_hi;
                r1.y = (o[n0][3] * a_hi + o2h.y * b_hi) * inv_hi;
                *(float2*)(out + ((size_t)b * TT + qt0 + r_lo) * HH + n0*8 + 2*tg) = r0;
                *(float2*)(out + ((size_t)b * TT + qt0 + r_hi) * HH + n0*8 + 2*tg) = r1;
            }
        } else {
            const int pidx = (b * 32 + qi) * 4 + ch;
            float* pod = g_po + (size_t)pidx * 4096;
#pragma unroll
            for (int n0 = 0; n0 < 8; n0++) {
                float2 o2l = *(float2*)(Om + (g    ) * PITCH + n0*8 + 2*tg);
                float2 o2h = *(float2*)(Om + (g + 8) * PITCH + n0*8 + 2*tg);
                float2 r0, r1;
                r0.x = o[n0][0] * a_lo + o2l.x * b_lo;
                r0.y = o[n0][1] * a_lo + o2l.y * b_lo;
                r1.x = o[n0][2] * a_hi + o2h.x * b_hi;
                r1.y = o[n0][3] * a_hi + o2h.y * b_hi;
                *(float2*)(pod + r_lo * 64 + n0*8 + 2*tg) = r0;
                *(float2*)(pod + r_hi * 64 + n0*8 + 2*tg) = r1;
            }
            if (tg == 0) {
                g_ml[pidx*128 + r_lo*2] = mf_lo; g_ml[pidx*128 + r_lo*2 + 1] = lm_lo;
                g_ml[pidx*128 + r_hi*2] = mf_hi; g_ml[pidx*128 + r_hi*2 + 1] = lm_hi;
            }
        }
    }
}

// ---------------------------------------------------------------------------
// Kernel 3: merge split-KV partials (qi >= 8).  grid (24, 4), block 1024.
// One float4 per thread (16x the parallelism of the old layout); chunk loop
// unrolled to fixed trip 4 with predication so partial loads issue in parallel.
// ---------------------------------------------------------------------------
__global__ __launch_bounds__(1024) void merge_kernel(float* __restrict__ out)
{
    const int qi  = 8 + blockIdx.x;
    const int b   = blockIdx.y;
    const int nch = (qi + 8) >> 3;        // 2..4
    const int tid = threadIdx.x;
    const int r   = tid >> 4;             // 0..63
    const int c4  = tid & 15;             // float4 within row
    const int pbase = (b * 32 + qi) * 4;

    float mv[4], lv[4], e[4];
    float mf = -INFINITY;
#pragma unroll
    for (int c = 0; c < 4; c++) {
        if (c < nch) {
            mv[c] = g_ml[(pbase + c)*128 + r*2];
            lv[c] = g_ml[(pbase + c)*128 + r*2 + 1];
            mf = fmaxf(mf, mv[c]);
        }
    }
    float wsum = 0.f;
#pragma unroll
    for (int c = 0; c < 4; c++)
        if (c < nch) { e[c] = ex2(mv[c] - mf); wsum += lv[c] * e[c]; }
    float inv = 1.0f / wsum;

    float4 a = make_float4(0.f, 0.f, 0.f, 0.f);
#pragma unroll
    for (int c = 0; c < 4; c++) {
        if (c < nch) {
            const float4 p = *(const float4*)(g_po + (size_t)(pbase + c)*4096 + r*64 + c4*4);
            a.x += e[c]*p.x; a.y += e[c]*p.y; a.z += e[c]*p.z; a.w += e[c]*p.w;
        }
    }
    a.x *= inv; a.y *= inv; a.z *= inv; a.w *= inv;
    *(float4*)(out + ((size_t)b * TT + qi * 64 + r) * HH + c4*4) = a;
}

// ---------------------------------------------------------------------------
extern "C" void kernel_launch(void* const* d_in, const int* in_sizes, int n_in,
                              void* d_out, int out_size)
{
    const float* x  = (const float*)d_in[0];
    const float* Wq = (const float*)d_in[1];
    const float* bq = (const float*)d_in[2];
    const float* Wk = (const float*)d_in[3];
    const float* bk = (const float*)d_in[4];
    const float* Wv = (const float*)d_in[5];
    const float* bv = (const float*)d_in[6];
    float* out = (float*)d_out;

    const int proj_smem = PJ_SM_FLOATS * sizeof(float);   // 110592
    cudaFuncSetAttribute(proj_kernel, cudaFuncAttributeMaxDynamicSharedMemorySize, proj_smem);
    proj_kernel<<<MM / 64, 256, proj_smem>>>(x, Wq, bq, Wk, bk, Wv, bv);

    const int smem_bytes = SM_FLOATS * sizeof(float);     // 104448
    cudaFuncSetAttribute(attn_kernel, cudaFuncAttributeMaxDynamicSharedMemorySize, smem_bytes);
    attn_kernel<<<dim3(80, BB), 256, smem_bytes>>>(out);

    merge_kernel<<<dim3(24, BB), 1024>>>(out);
}

// round 17
// speedup vs baseline: 1.1366x; 1.0051x over previous
#include <cuda_runtime.h>
#include <math.h>

#define BB 4
#define TT 2048
#define EE 1024
#define HH 64
#define MM (BB*TT)

// device scratch (module statics: allocation-free)
__device__ float g_q[MM*HH];
__device__ float g_k[MM*HH];
__device__ float g_v[MM*HH];
// split-KV partials: pidx = (b*32 + qtile)*4 + chunk   (chunk of 8 KV tiles)
__device__ float g_po[512*64*64];
__device__ float g_ml[512*64*2];

__device__ __forceinline__ unsigned f2tf32(float f) {
    unsigned u;
    asm("cvt.rna.tf32.f32 %0, %1;" : "=r"(u) : "f"(f));
    return u;
}
__device__ __forceinline__ unsigned u2tf32(unsigned ub) {
    unsigned u;
    asm("cvt.rna.tf32.f32 %0, %1;" : "=r"(u) : "f"(__uint_as_float(ub)));
    return u;
}
__device__ __forceinline__ float ex2(float x) {
    float y;
    asm("ex2.approx.ftz.f32 %0, %1;" : "=f"(y) : "f"(x));
    return y;
}
__device__ __forceinline__ void mma_tf32(float c[4], unsigned a0, unsigned a1,
                                         unsigned a2, unsigned a3,
                                         unsigned b0, unsigned b1) {
    asm volatile(
        "mma.sync.aligned.m16n8k8.row.col.f32.tf32.tf32.f32 "
        "{%0,%1,%2,%3}, {%4,%5,%6,%7}, {%8,%9}, {%0,%1,%2,%3};"
        : "+f"(c[0]), "+f"(c[1]), "+f"(c[2]), "+f"(c[3])
        : "r"(a0), "r"(a1), "r"(a2), "r"(a3), "r"(b0), "r"(b1));
}
#define LDSM4(r0,r1,r2,r3,addr) \
    asm volatile("ldmatrix.sync.aligned.m8n8.x4.shared.b16 {%0,%1,%2,%3}, [%4];" \
                 : "=r"(r0), "=r"(r1), "=r"(r2), "=r"(r3) : "r"(addr))

__device__ __forceinline__ void cp16(void* smem, const void* gmem) {
    unsigned sa = (unsigned)__cvta_generic_to_shared(smem);
    asm volatile("cp.async.cg.shared.global [%0], [%1], 16;" :: "r"(sa), "l"(gmem));
}
#define CP_COMMIT() asm volatile("cp.async.commit_group;")
#define CP_WAIT0()  asm volatile("cp.async.wait_group 0;")
#define CP_WAIT1()  asm volatile("cp.async.wait_group 1;")

// ---------------------------------------------------------------------------
// Kernel 1: QKV projection, ONE matrix per block (occupancy over fusion).
// grid (128, 3): x = 64-row tile, y = matrix (0:Q 1:K 2:V).
// block 256 (8 warps), warp tiling 2m x 2n x 2k, 32 K-chunks of 32,
// 3-stage cp.async ring.  Stage = X slab + W slab (2 x 64 x 36 floats,
// 18 KB) -> 54 KB total => multiple blocks/SM hide the chunk-chain stalls.
// kg=1 partials reduced into kg=0 via smem; bias + tf32 epilogue unchanged.
// ---------------------------------------------------------------------------
#define PJ_PITCH 36
#define PJ_MATF  (64*PJ_PITCH)            // 2304 floats per slab
#define PJ_STAGE (2*PJ_MATF)              // 4608 floats per stage
#define PJ_SM_FLOATS (3*PJ_STAGE)         // 13824 -> 55296 bytes

__global__ __launch_bounds__(256) void proj_kernel(
    const float* __restrict__ x,
    const float* __restrict__ Wq, const float* __restrict__ bq,
    const float* __restrict__ Wk, const float* __restrict__ bk,
    const float* __restrict__ Wv, const float* __restrict__ bv)
{
    extern __shared__ __align__(16) float psm[];

    const int row0 = blockIdx.x * 64;
    const int mat  = blockIdx.y;
    const int tid  = threadIdx.x;
    const int wid  = tid >> 5, l = tid & 31;
    const int g    = l >> 2, tg = l & 3;
    const int m0   = (wid & 1) * 32;
    const int n0   = ((wid >> 1) & 1) * 32;
    const int kg   = wid >> 2;

    const float* W    = (mat == 0) ? Wq : (mat == 1) ? Wk : Wv;
    const float* bias = (mat == 0) ? bq : (mat == 1) ? bk : bv;
    float* outp       = (mat == 0) ? g_q : (mat == 1) ? g_k : g_v;

    const float* srcp[2];
    srcp[0] = x + (size_t)row0 * EE;
    srcp[1] = W;

#define PPREF(kc) { \
    float* stage = psm + ((kc) % 3) * PJ_STAGE; \
    _Pragma("unroll") for (int t = 0; t < 4; t++) { \
        int idx = tid + t * 256;            /* 0..1023 */ \
        int sl  = idx >> 9;                 /* slab 0:X 1:W */ \
        int rem = idx & 511; \
        int row = rem >> 3, u = rem & 7; \
        cp16(stage + sl * PJ_MATF + row * PJ_PITCH + u * 4, \
             srcp[sl] + (size_t)row * EE + (kc) * 32 + u * 4); \
    } \
    CP_COMMIT(); }

    float acc[2][4][4];
#pragma unroll
    for (int mi = 0; mi < 2; mi++)
#pragma unroll
        for (int nf = 0; nf < 4; nf++)
#pragma unroll
            for (int i = 0; i < 4; i++) acc[mi][nf][i] = 0.0f;

    const unsigned sb = (unsigned)__cvta_generic_to_shared(psm);
    const unsigned aoffA[2] = {
        (unsigned)((m0 +      (l & 15)) * PJ_PITCH + ((l & 16) >> 2)),
        (unsigned)((m0 + 16 + (l & 15)) * PJ_PITCH + ((l & 16) >> 2)) };
    const unsigned boffB[2] = {
        (unsigned)((n0 +      (l & 7) + ((l & 16) >> 1)) * PJ_PITCH + ((l & 8) >> 1)),
        (unsigned)((n0 + 16 + (l & 7) + ((l & 16) >> 1)) * PJ_PITCH + ((l & 8) >> 1)) };

    PPREF(0); PPREF(1);

    for (int j = 0; j < 32; j++) {
        if (j < 31) { CP_WAIT1(); } else { CP_WAIT0(); }
        __syncthreads();

        const unsigned stg = sb + (j % 3) * (PJ_STAGE * 4);
#pragma unroll
        for (int k8 = 0; k8 < 2; k8++) {
            const unsigned kk = (kg * 16 + k8 * 8) * 4;
            unsigned a[2][4];
#pragma unroll
            for (int mi = 0; mi < 2; mi++) {
                LDSM4(a[mi][0], a[mi][1], a[mi][2], a[mi][3],
                      stg + aoffA[mi] * 4 + kk);
                a[mi][0] = u2tf32(a[mi][0]); a[mi][1] = u2tf32(a[mi][1]);
                a[mi][2] = u2tf32(a[mi][2]); a[mi][3] = u2tf32(a[mi][3]);
            }
            const unsigned mb = stg + PJ_MATF * 4;
#pragma unroll
            for (int np = 0; np < 2; np++) {
                unsigned b0, b1, b2, b3;
                LDSM4(b0, b1, b2, b3, mb + boffB[np] * 4 + kk);
                b0 = u2tf32(b0); b1 = u2tf32(b1);
                b2 = u2tf32(b2); b3 = u2tf32(b3);
#pragma unroll
                for (int mi = 0; mi < 2; mi++) {
                    mma_tf32(acc[mi][np*2    ], a[mi][0], a[mi][1], a[mi][2], a[mi][3], b0, b1);
                    mma_tf32(acc[mi][np*2 + 1], a[mi][0], a[mi][1], a[mi][2], a[mi][3], b2, b3);
                }
            }
        }
        if (j + 2 < 32) PPREF(j + 2);
    }
#undef PPREF

    // ---- kg-split reduction: warps 4-7 publish, warps 0-3 combine ----
    __syncthreads();
    if (kg == 1) {
        float* red = psm + (tid - 128) * 32;
#pragma unroll
        for (int mi = 0; mi < 2; mi++)
#pragma unroll
            for (int nf = 0; nf < 4; nf++)
#pragma unroll
                for (int i = 0; i < 4; i++)
                    red[(mi*4 + nf)*4 + i] = acc[mi][nf][i];
    }
    __syncthreads();
    if (kg == 0) {
        const float* red = psm + tid * 32;
#pragma unroll
        for (int mi = 0; mi < 2; mi++) {
#pragma unroll
            for (int nf = 0; nf < 4; nf++) {
                const float* rp = red + (mi*4 + nf)*4;
                int col = n0 + nf * 8 + 2 * tg;
                float b0 = bias[col], b1 = bias[col + 1];
                int r_lo = row0 + m0 + mi*16 + g;
                float2 v0, v1;
                v0.x = __uint_as_float(f2tf32(acc[mi][nf][0] + rp[0] + b0));
                v0.y = __uint_as_float(f2tf32(acc[mi][nf][1] + rp[1] + b1));
                v1.x = __uint_as_float(f2tf32(acc[mi][nf][2] + rp[2] + b0));
                v1.y = __uint_as_float(f2tf32(acc[mi][nf][3] + rp[3] + b1));
                *(float2*)(outp + (size_t)r_lo       * HH + col) = v0;
                *(float2*)(outp + (size_t)(r_lo + 8) * HH + col) = v1;
            }
        }
    }
}

// ---------------------------------------------------------------------------
// Kernel 2: causal flash attention (R14/R16: 102KB smem, 2 blocks/SM).
// ---------------------------------------------------------------------------
#define PITCH 68
#define TILE_F (64*PITCH)
#define KS_OFF 0
#define VS_OFF (2*TILE_F)
#define PS_OFF (4*TILE_F)
#define SM_FLOATS (PS_OFF + 8*16*PITCH)
#define SCL 0.18033688011112042f

__device__ __forceinline__ void attn_prefetch(
    float* sm, const float* kbase, const float* vbase,
    int tid, int tbase, int nt, int j)
{
#pragma unroll
    for (int t = 0; t < 16; t++) {
        int cidf = tid + t * 256;
        int sel  = cidf >> 10;
        int cid  = cidf & 1023;
        int row  = cid >> 4, c16 = cid & 15;
        int jt   = 2 * j + (sel & 1);
        if (jt < nt) {
            const float* src = ((sel >> 1) ? vbase : kbase)
                               + ((size_t)((tbase + jt) * 64 + row)) * HH + c16 * 4;
            float* dst = sm + ((sel >> 1) ? VS_OFF : KS_OFF)
                         + (sel & 1) * TILE_F + row * PITCH + c16 * 4;
            cp16(dst, src);
        }
    }
}

__global__ __launch_bounds__(256, 2) void attn_kernel(float* __restrict__ out)
{
    extern __shared__ float sm[];

    const int b   = blockIdx.y;
    const int tid = threadIdx.x;
    const int wid = tid >> 5, l = tid & 31, g = l >> 2, tg = l & 3;
    const int mt  = wid & 3;
    const int s   = wid >> 2;

    int qi = 0, ch = 0;
    {
        int wl = blockIdx.x, acc = 0;
        for (int ii = 31; ii >= 0; ii--) {
            int nc = (ii + 8) >> 3;
            if (wl < acc + nc) { qi = ii; ch = wl - acc; break; }
            acc += nc;
        }
    }
    const int qt0    = qi * 64;
    const int ntiles = qi + 1;
    const int nch    = (qi + 8) >> 3;
    const int tbase  = ch * 8;
    int nt = ntiles - tbase; if (nt > 8) nt = 8;
    const int ns = (nt + 1) >> 1;

    const float* kbase = g_k + (size_t)b * TT * HH;
    const float* vbase = g_v + (size_t)b * TT * HH;

    {
        const float* qsrc = g_q + ((size_t)b * TT + qt0) * HH;
#pragma unroll
        for (int t = 0; t < 4; t++) {
            int cid = tid + t * 256;
            int row = cid >> 4, c16 = cid & 15;
            cp16(sm + PS_OFF + row * PITCH + c16 * 4, qsrc + row * HH + c16 * 4);
        }
        attn_prefetch(sm, kbase, vbase, tid, tbase, nt, 0);
        CP_COMMIT();
    }

    const unsigned smu = (unsigned)__cvta_generic_to_shared(sm);
    const unsigned a16off = ((l & 15) * PITCH + ((l & 16) >> 2)) * 4;
    const unsigned bkoff  = (((l & 7) + ((l & 16) >> 1)) * PITCH + ((l & 8) >> 1)) * 4;
    const unsigned ps_u32 = smu + (PS_OFF + wid * 16 * PITCH) * 4 + a16off;
    const unsigned qs_u32 = smu + (PS_OFF + mt * 16 * PITCH) * 4 + a16off;

    unsigned qreg[8][4];
    float o[8][4];
    float m_lo = -INFINITY, m_hi = -INFINITY, l_lo = 0.f, l_hi = 0.f;
#pragma unroll
    for (int n = 0; n < 8; n++)
#pragma unroll
        for (int i = 0; i < 4; i++) o[n][i] = 0.0f;

    float* Ps = sm + PS_OFF + wid * (16 * PITCH);

    for (int j = 0; j < ns; j++) {
        CP_WAIT0();
        __syncthreads();

        if (j == 0) {
#pragma unroll
            for (int k8 = 0; k8 < 8; k8++)
                LDSM4(qreg[k8][0], qreg[k8][1], qreg[k8][2], qreg[k8][3],
                      qs_u32 + k8 * 32);
            __syncthreads();
        }

        const int jt = 2 * j + s;
        if (jt < nt) {
            const int k0 = (tbase + jt) * 64;
            const unsigned kb_u32 = smu + (KS_OFF + s * TILE_F) * 4 + bkoff;
            const float* Vb = sm + VS_OFF + s * TILE_F;

            float sc[8][4];
#pragma unroll
            for (int n = 0; n < 8; n++)
#pragma unroll
                for (int i = 0; i < 4; i++) sc[n][i] = 0.0f;
#pragma unroll
            for (int k8 = 0; k8 < 8; k8++) {
#pragma unroll
                for (int n0p = 0; n0p < 4; n0p++) {
                    unsigned b0, b1, b2, b3;
                    LDSM4(b0, b1, b2, b3,
                          kb_u32 + n0p * (16 * PITCH * 4) + k8 * 32);
                    mma_tf32(sc[n0p*2    ], qreg[k8][0], qreg[k8][1], qreg[k8][2], qreg[k8][3], b0, b1);
                    mma_tf32(sc[n0p*2 + 1], qreg[k8][0], qreg[k8][1], qreg[k8][2], qreg[k8][3], b2, b3);
                }
            }

            const int t_lo = qt0 + mt*16 + g;
            const int t_hi = t_lo + 8;
            float mx_lo = -INFINITY, mx_hi = -INFINITY;
#pragma unroll
            for (int n0 = 0; n0 < 8; n0++) {
                int c0 = k0 + n0*8 + 2*tg, c1 = c0 + 1;
                sc[n0][0] = (c0 <= t_lo) ? sc[n0][0] * SCL : -INFINITY;
                sc[n0][1] = (c1 <= t_lo) ? sc[n0][1] * SCL : -INFINITY;
                sc[n0][2] = (c0 <= t_hi) ? sc[n0][2] * SCL : -INFINITY;
                sc[n0][3] = (c1 <= t_hi) ? sc[n0][3] * SCL : -INFINITY;
                mx_lo = fmaxf(mx_lo, fmaxf(sc[n0][0], sc[n0][1]));
                mx_hi = fmaxf(mx_hi, fmaxf(sc[n0][2], sc[n0][3]));
            }
            mx_lo = fmaxf(mx_lo, __shfl_xor_sync(0xffffffffu, mx_lo, 1));
            mx_lo = fmaxf(mx_lo, __shfl_xor_sync(0xffffffffu, mx_lo, 2));
            mx_hi = fmaxf(mx_hi, __shfl_xor_sync(0xffffffffu, mx_hi, 1));
            mx_hi = fmaxf(mx_hi, __shfl_xor_sync(0xffffffffu, mx_hi, 2));
            float mn_lo = fmaxf(m_lo, mx_lo);
            float mn_hi = fmaxf(m_hi, mx_hi);
            float f_lo = ex2(m_lo - mn_lo);
            float f_hi = ex2(m_hi - mn_hi);

            float sum_lo = 0.f, sum_hi = 0.f;
#pragma unroll
            for (int n0 = 0; n0 < 8; n0++) {
                float p0 = ex2(sc[n0][0] - mn_lo);
                float p1 = ex2(sc[n0][1] - mn_lo);
                float p2 = ex2(sc[n0][2] - mn_hi);
                float p3 = ex2(sc[n0][3] - mn_hi);
                sum_lo += p0 + p1;
                sum_hi += p2 + p3;
                float2 w0, w1;
                w0.x = __uint_as_float(f2tf32(p0)); w0.y = __uint_as_float(f2tf32(p1));
                w1.x = __uint_as_float(f2tf32(p2)); w1.y = __uint_as_float(f2tf32(p3));
                *(float2*)(Ps + (g    ) * PITCH + n0*8 + 2*tg) = w0;
                *(float2*)(Ps + (g + 8) * PITCH + n0*8 + 2*tg) = w1;
            }
            sum_lo += __shfl_xor_sync(0xffffffffu, sum_lo, 1);
            sum_lo += __shfl_xor_sync(0xffffffffu, sum_lo, 2);
            sum_hi += __shfl_xor_sync(0xffffffffu, sum_hi, 1);
            sum_hi += __shfl_xor_sync(0xffffffffu, sum_hi, 2);
            l_lo = l_lo * f_lo + sum_lo;
            l_hi = l_hi * f_hi + sum_hi;
            m_lo = mn_lo; m_hi = mn_hi;
#pragma unroll
            for (int n0 = 0; n0 < 8; n0++) {
                o[n0][0] *= f_lo; o[n0][1] *= f_lo;
                o[n0][2] *= f_hi; o[n0][3] *= f_hi;
            }
            __syncwarp();

#pragma unroll
            for (int k8 = 0; k8 < 8; k8++) {
                unsigned a0, a1, a2, a3;
                LDSM4(a0, a1, a2, a3, ps_u32 + k8 * 32);
#pragma unroll
                for (int n0 = 0; n0 < 8; n0++) {
                    unsigned b0 = __float_as_uint(Vb[(k8*8 + tg    ) * PITCH + n0*8 + g]);
                    unsigned b1 = __float_as_uint(Vb[(k8*8 + tg + 4) * PITCH + n0*8 + g]);
                    mma_tf32(o[n0], a0, a1, a2, a3, b0, b1);
                }
            }
        }
        __syncthreads();
        if (j + 1 < ns) {
            attn_prefetch(sm, kbase, vbase, tid, tbase, nt, j + 1);
            CP_COMMIT();
        }
    }

    __syncthreads();
    float* Om = sm + PS_OFF + mt * (16 * PITCH);
    float* Ml = sm + PS_OFF + 4 * (16 * PITCH) + mt * 32;
    if (s == 1) {
#pragma unroll
        for (int n0 = 0; n0 < 8; n0++) {
            *(float2*)(Om + (g    ) * PITCH + n0*8 + 2*tg) = make_float2(o[n0][0], o[n0][1]);
            *(float2*)(Om + (g + 8) * PITCH + n0*8 + 2*tg) = make_float2(o[n0][2], o[n0][3]);
        }
        Ml[g] = m_lo; Ml[g + 8] = m_hi;
        Ml[16 + g] = l_lo; Ml[16 + 8 + g] = l_hi;
    }
    __syncthreads();
    if (s == 0) {
        float m2_lo = Ml[g], m2_hi = Ml[g + 8];
        float l2_lo = Ml[16 + g], l2_hi = Ml[16 + 8 + g];
        float mf_lo = fmaxf(m_lo, m2_lo), mf_hi = fmaxf(m_hi, m2_hi);
        float a_lo = ex2(m_lo - mf_lo), b_lo = ex2(m2_lo - mf_lo);
        float a_hi = ex2(m_hi - mf_hi), b_hi = ex2(m2_hi - mf_hi);
        float lm_lo = l_lo * a_lo + l2_lo * b_lo;
        float lm_hi = l_hi * a_hi + l2_hi * b_hi;
        const int r_lo = mt*16 + g, r_hi = r_lo + 8;

        if (nch == 1) {
            float inv_lo = 1.0f / lm_lo, inv_hi = 1.0f / lm_hi;
#pragma unroll
            for (int n0 = 0; n0 < 8; n0++) {
                float2 o2l = *(float2*)(Om + (g    ) * PITCH + n0*8 + 2*tg);
                float2 o2h = *(float2*)(Om + (g + 8) * PITCH + n0*8 + 2*tg);
                float2 r0, r1;
                r0.x = (o[n0][0] * a_lo + o2l.x * b_lo) * inv_lo;
                r0.y = (o[n0][1] * a_lo + o2l.y * b_lo) * inv_lo;
                r1.x = (o[n0][2] * a_hi + o2h.x * b_hi) * inv_hi;
                r1.y = (o[n0][3] * a_hi + o2h.y * b_hi) * inv_hi;
                *(float2*)(out + ((size_t)b * TT + qt0 + r_lo) * HH + n0*8 + 2*tg) = r0;
                *(float2*)(out + ((size_t)b * TT + qt0 + r_hi) * HH + n0*8 + 2*tg) = r1;
            }
        } else {
            const int pidx = (b * 32 + qi) * 4 + ch;
            float* pod = g_po + (size_t)pidx * 4096;
#pragma unroll
            for (int n0 = 0; n0 < 8; n0++) {
                float2 o2l = *(float2*)(Om + (g    ) * PITCH + n0*8 + 2*tg);
                float2 o2h = *(float2*)(Om + (g + 8) * PITCH + n0*8 + 2*tg);
                float2 r0, r1;
                r0.x = o[n0][0] * a_lo + o2l.x * b_lo;
                r0.y = o[n0][1] * a_lo + o2l.y * b_lo;
                r1.x = o[n0][2] * a_hi + o2h.x * b_hi;
                r1.y = o[n0][3] * a_hi + o2h.y * b_hi;
                *(float2*)(pod + r_lo * 64 + n0*8 + 2*tg) = r0;
                *(float2*)(pod + r_hi * 64 + n0*8 + 2*tg) = r1;
            }
            if (tg == 0) {
                g_ml[pidx*128 + r_lo*2] = mf_lo; g_ml[pidx*128 + r_lo*2 + 1] = lm_lo;
                g_ml[pidx*128 + r_hi*2] = mf_hi; g_ml[pidx*128 + r_hi*2 + 1] = lm_hi;
            }
        }
    }
}

// ---------------------------------------------------------------------------
// Kernel 3: merge split-KV partials (qi >= 8).  grid (24, 4), block 1024.
// ---------------------------------------------------------------------------
__global__ __launch_bounds__(1024) void merge_kernel(float* __restrict__ out)
{
    const int qi  = 8 + blockIdx.x;
    const int b   = blockIdx.y;
    const int nch = (qi + 8) >> 3;        // 2..4
    const int tid = threadIdx.x;
    const int r   = tid >> 4;             // 0..63
    const int c4  = tid & 15;             // float4 within row
    const int pbase = (b * 32 + qi) * 4;

    float mv[4], lv[4], e[4];
    float mf = -INFINITY;
#pragma unroll
    for (int c = 0; c < 4; c++) {
        if (c < nch) {
            mv[c] = g_ml[(pbase + c)*128 + r*2];
            lv[c] = g_ml[(pbase + c)*128 + r*2 + 1];
            mf = fmaxf(mf, mv[c]);
        }
    }
    float wsum = 0.f;
#pragma unroll
    for (int c = 0; c < 4; c++)
        if (c < nch) { e[c] = ex2(mv[c] - mf); wsum += lv[c] * e[c]; }
    float inv = 1.0f / wsum;

    float4 a = make_float4(0.f, 0.f, 0.f, 0.f);
#pragma unroll
    for (int c = 0; c < 4; c++) {
        if (c < nch) {
            const float4 p = *(const float4*)(g_po + (size_t)(pbase + c)*4096 + r*64 + c4*4);
            a.x += e[c]*p.x; a.y += e[c]*p.y; a.z += e[c]*p.z; a.w += e[c]*p.w;
        }
    }
    a.x *= inv; a.y *= inv; a.z *= inv; a.w *= inv;
    *(float4*)(out + ((size_t)b * TT + qi * 64 + r) * HH + c4*4) = a;
}

// ---------------------------------------------------------------------------
extern "C" void kernel_launch(void* const* d_in, const int* in_sizes, int n_in,
                              void* d_out, int out_size)
{
    const float* x  = (const float*)d_in[0];
    const float* Wq = (const float*)d_in[1];
    const float* bq = (const float*)d_in[2];
    const float* Wk = (const float*)d_in[3];
    const float* bk = (const float*)d_in[4];
    const float* Wv = (const float*)d_in[5];
    const float* bv = (const float*)d_in[6];
    float* out = (float*)d_out;

    const int proj_smem = PJ_SM_FLOATS * sizeof(float);   // 55296
    cudaFuncSetAttribute(proj_kernel, cudaFuncAttributeMaxDynamicSharedMemorySize, proj_smem);
    proj_kernel<<<dim3(MM / 64, 3), 256, proj_smem>>>(x, Wq, bq, Wk, bk, Wv, bv);

    const int smem_bytes = SM_FLOATS * sizeof(float);     // 104448
    cudaFuncSetAttribute(attn_kernel, cudaFuncAttributeMaxDynamicSharedMemorySize, smem_bytes);
    attn_kernel<<<dim3(80, BB), 256, smem_bytes>>>(out);

    merge_kernel<<<dim3(24, BB), 1024>>>(out);
}